// round 1
// baseline (speedup 1.0000x reference)
#include <cuda_runtime.h>
#include <cstdint>

#define D 128
#define MAXN 65536
#define MAXE 1048576
#define NLAYER 5

// ---------------- static scratch (no allocations allowed) ----------------
__device__ float g_h[(size_t)MAXN * D];
__device__ float g_agg[(size_t)MAXN * D];
__device__ float g_hidden[(size_t)MAXN * 2 * D];
__device__ float g_h2[(size_t)MAXN * D];
__device__ int   g_deg[MAXN];
__device__ int   g_rowptr[MAXN + 1];
__device__ int   g_cursor[MAXN];
__device__ int   g_perm[MAXE];
__device__ int   g_bsum[512];
__device__ float g_bnstat[2 * D];

// ---------------- CSR build ----------------
__global__ void k_zero_deg(int N) {
    int i = blockIdx.x * blockDim.x + threadIdx.x;
    if (i < N) g_deg[i] = 0;
}

__global__ void k_count(const int* __restrict__ ei, int E) {
    int e = blockIdx.x * blockDim.x + threadIdx.x;
    if (e < E) atomicAdd(&g_deg[ei[E + e]], 1);
}

__global__ void k_scan_block(int N) {
    __shared__ int s[256];
    int tid = threadIdx.x;
    int i = blockIdx.x * 256 + tid;
    int v = (i < N) ? g_deg[i] : 0;
    s[tid] = v;
    __syncthreads();
    #pragma unroll
    for (int off = 1; off < 256; off <<= 1) {
        int t = (tid >= off) ? s[tid - off] : 0;
        __syncthreads();
        s[tid] += t;
        __syncthreads();
    }
    if (i < N) g_rowptr[i] = s[tid] - v;            // exclusive within block
    if (tid == 255) g_bsum[blockIdx.x] = s[255];    // block total
}

__global__ void k_scan_top(int nb) {
    __shared__ int s[256];
    int tid = threadIdx.x;
    int v = (tid < nb) ? g_bsum[tid] : 0;
    s[tid] = v;
    __syncthreads();
    #pragma unroll
    for (int off = 1; off < 256; off <<= 1) {
        int t = (tid >= off) ? s[tid - off] : 0;
        __syncthreads();
        s[tid] += t;
        __syncthreads();
    }
    if (tid < nb) g_bsum[tid] = s[tid] - v;         // exclusive block offsets
}

__global__ void k_addoff(int N, int E) {
    int tid = threadIdx.x;
    int i = blockIdx.x * 256 + tid;
    if (i < N) {
        int r = g_rowptr[i] + g_bsum[blockIdx.x];
        g_rowptr[i] = r;
        g_cursor[i] = r;
    }
    if (i == 0) g_rowptr[N] = E;
}

__global__ void k_fill(const int* __restrict__ ei, int E) {
    int e = blockIdx.x * blockDim.x + threadIdx.x;
    if (e < E) {
        int dst = ei[E + e];
        int pos = atomicAdd(&g_cursor[dst], 1);
        g_perm[pos] = e;
    }
}

// ---------------- atom encoder ----------------
__global__ void k_atom(const int* __restrict__ x,
                       const float* __restrict__ ae1,
                       const float* __restrict__ ae2, int N) {
    int idx = blockIdx.x * blockDim.x + threadIdx.x;
    if (idx >= N * D) return;
    int n = idx >> 7;
    int d = idx & (D - 1);
    g_h[idx] = ae1[x[2 * n] * D + d] + ae2[x[2 * n + 1] * D + d];
}

// ---------------- aggregation: warp per node, float4 lanes ----------------
__global__ void k_aggregate(const int* __restrict__ ei,
                            const int* __restrict__ ea,
                            const float* __restrict__ be1,   // this layer, [7][128]
                            const float* __restrict__ be2,   // this layer, [4][128]
                            int N, int E) {
    int gw = (blockIdx.x * blockDim.x + threadIdx.x) >> 5;
    int lane = threadIdx.x & 31;
    if (gw >= N) return;
    int n = gw;
    const float4* h4 = (const float4*)g_h;

    float4 acc = h4[(size_t)n * 32 + lane];
    // self-loop edge: bond type 6, dir 3
    float4 s1 = *(const float4*)&be1[6 * D + lane * 4];
    float4 s2 = *(const float4*)&be2[3 * D + lane * 4];
    acc.x += s1.x + s2.x; acc.y += s1.y + s2.y;
    acc.z += s1.z + s2.z; acc.w += s1.w + s2.w;

    int beg = g_rowptr[n];
    int end = g_rowptr[n + 1];
    for (int k = beg; k < end; k++) {
        int e  = g_perm[k];
        int s  = ei[e];
        int a0 = ea[2 * e];
        int a1 = ea[2 * e + 1];
        float4 hv  = h4[(size_t)s * 32 + lane];
        float4 b1v = *(const float4*)&be1[a0 * D + lane * 4];
        float4 b2v = *(const float4*)&be2[a1 * D + lane * 4];
        acc.x += hv.x + b1v.x + b2v.x;
        acc.y += hv.y + b1v.y + b2v.y;
        acc.z += hv.z + b1v.z + b2v.z;
        acc.w += hv.w + b1v.w + b2v.w;
    }
    ((float4*)g_agg)[(size_t)n * 32 + lane] = acc;
}

// ---------------- SGEMM: C[M,Nc] = A[M,K] @ W[K,Nc] + bias, optional ReLU ----
// BM=128, BN=64, BK=16, 256 threads, 8x4 microtile.
template <bool RELU>
__global__ void __launch_bounds__(256) sgemm(const float* __restrict__ A,
                                             const float* __restrict__ W,
                                             const float* __restrict__ bias,
                                             float* __restrict__ C,
                                             int M, int K, int Nc) {
    const int BM = 128, BN = 64, BK = 16;
    __shared__ float As[BK][BM];
    __shared__ float Bs[BK][BN];
    int tid = threadIdx.x;
    int m0 = blockIdx.x * BM;
    int n0 = blockIdx.y * BN;
    int tr = tid >> 4;   // 0..15 -> rows tr*8..tr*8+7
    int tc = tid & 15;   // 0..15 -> cols tc*4..tc*4+3

    float acc[8][4];
    #pragma unroll
    for (int i = 0; i < 8; i++)
        #pragma unroll
        for (int j = 0; j < 4; j++) acc[i][j] = 0.f;

    for (int k0 = 0; k0 < K; k0 += BK) {
        // A tile: 128x16 floats = 512 float4, 2 per thread, stored transposed
        #pragma unroll
        for (int j = tid; j < 512; j += 256) {
            int row = j >> 2;
            int kc = (j & 3) << 2;
            float4 v = make_float4(0.f, 0.f, 0.f, 0.f);
            if (m0 + row < M)
                v = *(const float4*)&A[(size_t)(m0 + row) * K + k0 + kc];
            As[kc + 0][row] = v.x;
            As[kc + 1][row] = v.y;
            As[kc + 2][row] = v.z;
            As[kc + 3][row] = v.w;
        }
        // B tile: 16x64 floats = 256 float4, 1 per thread
        {
            int row = tid >> 4;
            int c4 = tid & 15;
            *(float4*)&Bs[row][c4 * 4] =
                *(const float4*)&W[(size_t)(k0 + row) * Nc + n0 + c4 * 4];
        }
        __syncthreads();
        #pragma unroll
        for (int kk = 0; kk < BK; kk++) {
            float a[8], b[4];
            *(float4*)&a[0] = *(const float4*)&As[kk][tr * 8];
            *(float4*)&a[4] = *(const float4*)&As[kk][tr * 8 + 4];
            *(float4*)&b[0] = *(const float4*)&Bs[kk][tc * 4];
            #pragma unroll
            for (int i = 0; i < 8; i++)
                #pragma unroll
                for (int j = 0; j < 4; j++)
                    acc[i][j] += a[i] * b[j];
        }
        __syncthreads();
    }

    float bv[4];
    *(float4*)bv = *(const float4*)&bias[n0 + tc * 4];
    #pragma unroll
    for (int i = 0; i < 8; i++) {
        int row = m0 + tr * 8 + i;
        if (row < M) {
            float4 o;
            o.x = acc[i][0] + bv[0];
            o.y = acc[i][1] + bv[1];
            o.z = acc[i][2] + bv[2];
            o.w = acc[i][3] + bv[3];
            if (RELU) {
                o.x = fmaxf(o.x, 0.f); o.y = fmaxf(o.y, 0.f);
                o.z = fmaxf(o.z, 0.f); o.w = fmaxf(o.w, 0.f);
            }
            *(float4*)&C[(size_t)row * Nc + n0 + tc * 4] = o;
        }
    }
}

// ---------------- batchnorm ----------------
__global__ void k_bn_zero() {
    if (threadIdx.x < 2 * D) g_bnstat[threadIdx.x] = 0.f;
}

__global__ void k_bn_stats(int N) {
    int c = threadIdx.x;  // 128 threads
    float s = 0.f, q = 0.f;
    for (int r = blockIdx.x; r < N; r += gridDim.x) {
        float v = g_h2[(size_t)r * D + c];
        s += v;
        q += v * v;
    }
    atomicAdd(&g_bnstat[c], s);
    atomicAdd(&g_bnstat[D + c], q);
}

__global__ void k_bn_apply(float* __restrict__ dst,
                           const float* __restrict__ gamma,
                           const float* __restrict__ beta,
                           int N, int relu) {
    int idx = blockIdx.x * blockDim.x + threadIdx.x;
    if (idx >= N * D) return;
    int c = idx & (D - 1);
    float invN = 1.0f / (float)N;
    float mu = g_bnstat[c] * invN;
    float var = g_bnstat[D + c] * invN - mu * mu;
    float istd = rsqrtf(var + 1e-5f);
    float v = (g_h2[idx] - mu) * istd * gamma[c] + beta[c];
    if (relu) v = fmaxf(v, 0.f);
    dst[idx] = v;
}

// ---------------- launch ----------------
extern "C" void kernel_launch(void* const* d_in, const int* in_sizes, int n_in,
                              void* d_out, int out_size) {
    const int*   x     = (const int*)d_in[0];
    const int*   ei    = (const int*)d_in[1];
    const int*   ea    = (const int*)d_in[2];
    const float* ae1   = (const float*)d_in[3];
    const float* ae2   = (const float*)d_in[4];
    const float* be1   = (const float*)d_in[5];  // [5][7][128]
    const float* be2   = (const float*)d_in[6];  // [5][4][128]
    const float* W1    = (const float*)d_in[7];  // [5][128][256]
    const float* b1    = (const float*)d_in[8];  // [5][256]
    const float* W2    = (const float*)d_in[9];  // [5][256][128]
    const float* b2    = (const float*)d_in[10]; // [5][128]
    const float* gamma = (const float*)d_in[11]; // [5][128]
    const float* beta  = (const float*)d_in[12]; // [5][128]

    int N = in_sizes[0] / 2;
    int E = in_sizes[1] / 2;

    float *p_agg, *p_hidden, *p_h2, *p_h;
    cudaGetSymbolAddress((void**)&p_agg, g_agg);
    cudaGetSymbolAddress((void**)&p_hidden, g_hidden);
    cudaGetSymbolAddress((void**)&p_h2, g_h2);
    cudaGetSymbolAddress((void**)&p_h, g_h);
    (void)p_h2;

    int nb = (N + 255) / 256;

    // CSR build (by destination)
    k_zero_deg<<<(N + 255) / 256, 256>>>(N);
    k_count<<<(E + 255) / 256, 256>>>(ei, E);
    k_scan_block<<<nb, 256>>>(N);
    k_scan_top<<<1, 256>>>(nb);
    k_addoff<<<nb, 256>>>(N, E);
    k_fill<<<(E + 255) / 256, 256>>>(ei, E);

    // atom encoder
    k_atom<<<((size_t)N * D + 255) / 256, 256>>>(x, ae1, ae2, N);

    for (int l = 0; l < NLAYER; l++) {
        const float* be1L = be1 + (size_t)l * 7 * D;
        const float* be2L = be2 + (size_t)l * 4 * D;

        // aggregate (warp per node)
        int totalThreads = N * 32;
        k_aggregate<<<(totalThreads + 255) / 256, 256>>>(ei, ea, be1L, be2L, N, E);

        // MLP: hidden = relu(agg @ W1 + b1); h2 = hidden @ W2 + b2
        dim3 g1((N + 127) / 128, 2 * D / 64);
        sgemm<true><<<g1, 256>>>(p_agg, W1 + (size_t)l * D * 2 * D,
                                 b1 + (size_t)l * 2 * D, p_hidden, N, D, 2 * D);
        dim3 g2((N + 127) / 128, D / 64);
        sgemm<false><<<g2, 256>>>(p_hidden, W2 + (size_t)l * 2 * D * D,
                                  b2 + (size_t)l * D, p_h2, N, 2 * D, D);

        // batchnorm (+relu except last layer)
        k_bn_zero<<<1, 256>>>();
        k_bn_stats<<<256, 128>>>(N);
        float* dst = (l == NLAYER - 1) ? (float*)d_out : p_h;
        k_bn_apply<<<((size_t)N * D + 255) / 256, 256>>>(
            dst, gamma + (size_t)l * D, beta + (size_t)l * D, N, l < NLAYER - 1);
    }
}

// round 3
// speedup vs baseline: 1.4287x; 1.4287x over previous
#include <cuda_runtime.h>
#include <cuda_bf16.h>
#include <cstdint>

#define D 128
#define MAXN 65536
#define MAXE 1048576
#define NLAYER 5

// ---------------- static scratch (no allocations allowed) ----------------
__device__ float g_h[(size_t)MAXN * D];
__device__ float g_agg[(size_t)MAXN * D];
__device__ float g_hidden[(size_t)MAXN * 2 * D];
__device__ float g_h2[(size_t)MAXN * D];
__device__ int   g_deg[MAXN];
__device__ int   g_rowptr[MAXN + 1];
__device__ int   g_cursor[MAXN];
__device__ int   g_perm[MAXE];
__device__ int   g_bsum[512];
__device__ float g_bnstat[2 * D];
// split-precision transposed weights: W^T as [N][K] bf16 hi/lo
__device__ __nv_bfloat16 g_w1h[NLAYER * 256 * 128];
__device__ __nv_bfloat16 g_w1l[NLAYER * 256 * 128];
__device__ __nv_bfloat16 g_w2h[NLAYER * 128 * 256];
__device__ __nv_bfloat16 g_w2l[NLAYER * 128 * 256];

// ---------------- CSR build ----------------
__global__ void k_zero_deg(int N) {
    int i = blockIdx.x * blockDim.x + threadIdx.x;
    if (i < N) g_deg[i] = 0;
}

__global__ void k_count(const int* __restrict__ ei, int E) {
    int e = blockIdx.x * blockDim.x + threadIdx.x;
    if (e < E) atomicAdd(&g_deg[ei[E + e]], 1);
}

__global__ void k_scan_block(int N) {
    __shared__ int s[256];
    int tid = threadIdx.x;
    int i = blockIdx.x * 256 + tid;
    int v = (i < N) ? g_deg[i] : 0;
    s[tid] = v;
    __syncthreads();
    #pragma unroll
    for (int off = 1; off < 256; off <<= 1) {
        int t = (tid >= off) ? s[tid - off] : 0;
        __syncthreads();
        s[tid] += t;
        __syncthreads();
    }
    if (i < N) g_rowptr[i] = s[tid] - v;
    if (tid == 255) g_bsum[blockIdx.x] = s[255];
}

__global__ void k_scan_top(int nb) {
    __shared__ int s[256];
    int tid = threadIdx.x;
    int v = (tid < nb) ? g_bsum[tid] : 0;
    s[tid] = v;
    __syncthreads();
    #pragma unroll
    for (int off = 1; off < 256; off <<= 1) {
        int t = (tid >= off) ? s[tid - off] : 0;
        __syncthreads();
        s[tid] += t;
        __syncthreads();
    }
    if (tid < nb) g_bsum[tid] = s[tid] - v;
}

__global__ void k_addoff(int N, int E) {
    int tid = threadIdx.x;
    int i = blockIdx.x * 256 + tid;
    if (i < N) {
        int r = g_rowptr[i] + g_bsum[blockIdx.x];
        g_rowptr[i] = r;
        g_cursor[i] = r;
    }
    if (i == 0) g_rowptr[N] = E;
}

__global__ void k_fill(const int* __restrict__ ei, int E) {
    int e = blockIdx.x * blockDim.x + threadIdx.x;
    if (e < E) {
        int dst = ei[E + e];
        int pos = atomicAdd(&g_cursor[dst], 1);
        g_perm[pos] = e;
    }
}

// ---------------- weight prep: transpose + bf16 split ----------------
__global__ void k_prep_w(const float* __restrict__ W1, const float* __restrict__ W2) {
    int idx = blockIdx.x * blockDim.x + threadIdx.x;
    if (idx >= NLAYER * 256 * 128) return;
    int l = idx >> 15;
    int r = idx & 32767;
    // W1: [128 k][256 n] -> w1t[n*128 + k]
    {
        int n = r >> 7, k = r & 127;
        float v = W1[(size_t)l * 32768 + (size_t)k * 256 + n];
        __nv_bfloat16 h = __float2bfloat16(v);
        g_w1h[idx] = h;
        g_w1l[idx] = __float2bfloat16(v - __bfloat162float(h));
    }
    // W2: [256 k][128 n] -> w2t[n*256 + k]
    {
        int n = r >> 8, k = r & 255;
        float v = W2[(size_t)l * 32768 + (size_t)k * 128 + n];
        __nv_bfloat16 h = __float2bfloat16(v);
        g_w2h[idx] = h;
        g_w2l[idx] = __float2bfloat16(v - __bfloat162float(h));
    }
}

// ---------------- atom encoder ----------------
__global__ void k_atom(const int* __restrict__ x,
                       const float* __restrict__ ae1,
                       const float* __restrict__ ae2, int N) {
    int idx = blockIdx.x * blockDim.x + threadIdx.x;
    if (idx >= N * D) return;
    int n = idx >> 7;
    int d = idx & (D - 1);
    g_h[idx] = ae1[x[2 * n] * D + d] + ae2[x[2 * n + 1] * D + d];
}

// ---------------- aggregation: warp per node, float4 lanes ----------------
__global__ void k_aggregate(const int* __restrict__ ei,
                            const int* __restrict__ ea,
                            const float* __restrict__ be1,
                            const float* __restrict__ be2,
                            int N, int E) {
    int gw = (blockIdx.x * blockDim.x + threadIdx.x) >> 5;
    int lane = threadIdx.x & 31;
    if (gw >= N) return;
    int n = gw;
    const float4* h4 = (const float4*)g_h;

    float4 acc = h4[(size_t)n * 32 + lane];
    float4 s1 = *(const float4*)&be1[6 * D + lane * 4];
    float4 s2 = *(const float4*)&be2[3 * D + lane * 4];
    acc.x += s1.x + s2.x; acc.y += s1.y + s2.y;
    acc.z += s1.z + s2.z; acc.w += s1.w + s2.w;

    int beg = g_rowptr[n];
    int end = g_rowptr[n + 1];
    for (int k = beg; k < end; k++) {
        int e  = g_perm[k];
        int s  = ei[e];
        int a0 = ea[2 * e];
        int a1 = ea[2 * e + 1];
        float4 hv  = h4[(size_t)s * 32 + lane];
        float4 b1v = *(const float4*)&be1[a0 * D + lane * 4];
        float4 b2v = *(const float4*)&be2[a1 * D + lane * 4];
        acc.x += hv.x + b1v.x + b2v.x;
        acc.y += hv.y + b1v.y + b2v.y;
        acc.z += hv.z + b1v.z + b2v.z;
        acc.w += hv.w + b1v.w + b2v.w;
    }
    ((float4*)g_agg)[(size_t)n * 32 + lane] = acc;
}

// ---------------- mma.sync bf16 split GEMM ----------------
// C[M, Nc] = A[M,K] @ W[K,Nc] + bias  (W given transposed [Nc][K] bf16 hi/lo)
// CTA tile 128x128, 8 warps (2x4), warp tile 64x32, K chunked by 128.
// D = Ah*Bh + Ah*Bl + Al*Bh in fp32 accumulators.

#define SM_PITCH 136  // bf16 elements per smem row (128 + 8 pad)

__device__ __forceinline__ uint32_t smem_u32(const void* p) {
    uint32_t a;
    asm("{ .reg .u64 t; cvta.to.shared.u64 t, %1; cvt.u32.u64 %0, t; }"
        : "=r"(a) : "l"(p));
    return a;
}

__device__ __forceinline__ void ldmx4(uint32_t* r, uint32_t addr) {
    asm volatile("ldmatrix.sync.aligned.m8n8.x4.shared.b16 {%0,%1,%2,%3}, [%4];"
                 : "=r"(r[0]), "=r"(r[1]), "=r"(r[2]), "=r"(r[3]) : "r"(addr));
}

__device__ __forceinline__ void mma16816(float* c, const uint32_t* a,
                                         const uint32_t* b) {
    asm volatile(
        "mma.sync.aligned.m16n8k16.row.col.f32.bf16.bf16.f32 "
        "{%0,%1,%2,%3}, {%4,%5,%6,%7}, {%8,%9}, {%0,%1,%2,%3};"
        : "+f"(c[0]), "+f"(c[1]), "+f"(c[2]), "+f"(c[3])
        : "r"(a[0]), "r"(a[1]), "r"(a[2]), "r"(a[3]), "r"(b[0]), "r"(b[1]));
}

template <bool RELU>
__global__ void __launch_bounds__(256, 1)
mma_gemm(const float* __restrict__ A,
         const __nv_bfloat16* __restrict__ Bh_g,
         const __nv_bfloat16* __restrict__ Bl_g,
         const float* __restrict__ bias,
         float* __restrict__ C, int M, int K, int Nc) {
    extern __shared__ __align__(16) char smem[];
    // byte offsets
    const int SZ = 128 * SM_PITCH * 2;  // 34816 per buffer
    char* pAh = smem;
    char* pAl = smem + SZ;
    char* pBh = smem + 2 * SZ;
    char* pBl = smem + 3 * SZ;
    uint32_t sAh = smem_u32(pAh), sAl = sAh + SZ, sBh = sAh + 2 * SZ,
             sBl = sAh + 3 * SZ;

    int tid = threadIdx.x;
    int lane = tid & 31, w = tid >> 5;
    int wm = (w & 1) * 64;        // warp m offset in tile
    int wn = (w >> 1) * 32;       // warp n offset in tile
    int m0 = blockIdx.x * 128;
    int n0 = blockIdx.y * 128;

    float acc[4][4][4];
    #pragma unroll
    for (int i = 0; i < 4; i++)
        #pragma unroll
        for (int j = 0; j < 4; j++)
            #pragma unroll
            for (int q = 0; q < 4; q++) acc[i][j][q] = 0.f;

    const int nchunk = K >> 7;
    for (int c = 0; c < nchunk; c++) {
        if (c > 0) __syncthreads();
        int k0 = c << 7;

        // A: 128 rows x 128 fp32 -> bf16 hi/lo in smem
        {
            const float* Ab = A + (size_t)m0 * K + k0;
            #pragma unroll
            for (int it = 0; it < 16; it++) {
                int idx = tid + it * 256;          // 0..4095
                int r = idx >> 5, c4 = idx & 31;   // c4: float4 idx in row
                float4 v = make_float4(0.f, 0.f, 0.f, 0.f);
                if (m0 + r < M)
                    v = *(const float4*)(Ab + (size_t)r * K + c4 * 4);
                __nv_bfloat16 h0 = __float2bfloat16(v.x);
                __nv_bfloat16 h1 = __float2bfloat16(v.y);
                __nv_bfloat16 h2 = __float2bfloat16(v.z);
                __nv_bfloat16 h3 = __float2bfloat16(v.w);
                __nv_bfloat16 l0 = __float2bfloat16(v.x - __bfloat162float(h0));
                __nv_bfloat16 l1 = __float2bfloat16(v.y - __bfloat162float(h1));
                __nv_bfloat16 l2 = __float2bfloat16(v.z - __bfloat162float(h2));
                __nv_bfloat16 l3 = __float2bfloat16(v.w - __bfloat162float(h3));
                uint32_t hp0 = (uint32_t)__bfloat16_as_ushort(h0) |
                               ((uint32_t)__bfloat16_as_ushort(h1) << 16);
                uint32_t hp1 = (uint32_t)__bfloat16_as_ushort(h2) |
                               ((uint32_t)__bfloat16_as_ushort(h3) << 16);
                uint32_t lp0 = (uint32_t)__bfloat16_as_ushort(l0) |
                               ((uint32_t)__bfloat16_as_ushort(l1) << 16);
                uint32_t lp1 = (uint32_t)__bfloat16_as_ushort(l2) |
                               ((uint32_t)__bfloat16_as_ushort(l3) << 16);
                int boff = (r * SM_PITCH + c4 * 4) * 2;
                *(uint2*)(pAh + boff) = make_uint2(hp0, hp1);
                *(uint2*)(pAl + boff) = make_uint2(lp0, lp1);
            }
        }
        // B: 128 n-rows x 128 bf16 (already [N][K])
        {
            #pragma unroll
            for (int it = 0; it < 8; it++) {
                int idx = tid + it * 256;          // 0..2047
                int n = idx >> 4, q = idx & 15;    // q: 16B chunk in row
                size_t gidx = (size_t)(n0 + n) * K + k0 + q * 8;
                int boff = (n * SM_PITCH + q * 8) * 2;
                *(uint4*)(pBh + boff) = *(const uint4*)(Bh_g + gidx);
                *(uint4*)(pBl + boff) = *(const uint4*)(Bl_g + gidx);
            }
        }
        __syncthreads();

        #pragma unroll
        for (int ks = 0; ks < 8; ks++) {
            uint32_t aH[4][4], aL[4][4], bH[4][2], bL[4][2];
            // A fragments: 4 m16 tiles
            int arow = wm + (lane & 15);
            int acol = ks * 16 + (lane >> 4) * 8;
            #pragma unroll
            for (int i = 0; i < 4; i++) {
                uint32_t off = (uint32_t)(((arow + i * 16) * SM_PITCH + acol) * 2);
                ldmx4(aH[i], sAh + off);
                ldmx4(aL[i], sAl + off);
            }
            // B fragments: 2 x (pair of n8 tiles)
            int brow = wn + ((lane >> 4) << 3) + (lane & 7);
            int bcol = ks * 16 + ((lane >> 3) & 1) * 8;
            #pragma unroll
            for (int p = 0; p < 2; p++) {
                uint32_t off = (uint32_t)(((brow + p * 16) * SM_PITCH + bcol) * 2);
                uint32_t t[4];
                ldmx4(t, sBh + off);
                bH[2 * p][0] = t[0]; bH[2 * p][1] = t[1];
                bH[2 * p + 1][0] = t[2]; bH[2 * p + 1][1] = t[3];
                ldmx4(t, sBl + off);
                bL[2 * p][0] = t[0]; bL[2 * p][1] = t[1];
                bL[2 * p + 1][0] = t[2]; bL[2 * p + 1][1] = t[3];
            }
            #pragma unroll
            for (int i = 0; i < 4; i++)
                #pragma unroll
                for (int j = 0; j < 4; j++) {
                    mma16816(acc[i][j], aH[i], bH[j]);
                    mma16816(acc[i][j], aH[i], bL[j]);
                    mma16816(acc[i][j], aL[i], bH[j]);
                }
        }
    }

    // epilogue: bias (+relu), guarded stores
    #pragma unroll
    for (int i = 0; i < 4; i++) {
        int r0 = m0 + wm + i * 16 + (lane >> 2);
        #pragma unroll
        for (int j = 0; j < 4; j++) {
            int col = n0 + wn + j * 8 + (lane & 3) * 2;
            float bx = __ldg(&bias[col]);
            float by = __ldg(&bias[col + 1]);
            float v0 = acc[i][j][0] + bx, v1 = acc[i][j][1] + by;
            float v2 = acc[i][j][2] + bx, v3 = acc[i][j][3] + by;
            if (RELU) {
                v0 = fmaxf(v0, 0.f); v1 = fmaxf(v1, 0.f);
                v2 = fmaxf(v2, 0.f); v3 = fmaxf(v3, 0.f);
            }
            if (r0 < M)
                *(float2*)&C[(size_t)r0 * Nc + col] = make_float2(v0, v1);
            if (r0 + 8 < M)
                *(float2*)&C[(size_t)(r0 + 8) * Nc + col] = make_float2(v2, v3);
        }
    }
}

// ---------------- batchnorm ----------------
__global__ void k_bn_zero() {
    if (threadIdx.x < 2 * D) g_bnstat[threadIdx.x] = 0.f;
}

__global__ void k_bn_stats(int N) {
    int c = threadIdx.x;
    float s = 0.f, q = 0.f;
    for (int r = blockIdx.x; r < N; r += gridDim.x) {
        float v = g_h2[(size_t)r * D + c];
        s += v;
        q += v * v;
    }
    atomicAdd(&g_bnstat[c], s);
    atomicAdd(&g_bnstat[D + c], q);
}

__global__ void k_bn_apply(float* __restrict__ dst,
                           const float* __restrict__ gamma,
                           const float* __restrict__ beta,
                           int N, int relu) {
    int idx = blockIdx.x * blockDim.x + threadIdx.x;
    if (idx >= N * D) return;
    int c = idx & (D - 1);
    float invN = 1.0f / (float)N;
    float mu = g_bnstat[c] * invN;
    float var = g_bnstat[D + c] * invN - mu * mu;
    float istd = rsqrtf(var + 1e-5f);
    float v = (g_h2[idx] - mu) * istd * gamma[c] + beta[c];
    if (relu) v = fmaxf(v, 0.f);
    dst[idx] = v;
}

// ---------------- launch ----------------
extern "C" void kernel_launch(void* const* d_in, const int* in_sizes, int n_in,
                              void* d_out, int out_size) {
    const int*   x     = (const int*)d_in[0];
    const int*   ei    = (const int*)d_in[1];
    const int*   ea    = (const int*)d_in[2];
    const float* ae1   = (const float*)d_in[3];
    const float* ae2   = (const float*)d_in[4];
    const float* be1   = (const float*)d_in[5];
    const float* be2   = (const float*)d_in[6];
    const float* W1    = (const float*)d_in[7];
    const float* b1    = (const float*)d_in[8];
    const float* W2    = (const float*)d_in[9];
    const float* b2    = (const float*)d_in[10];
    const float* gamma = (const float*)d_in[11];
    const float* beta  = (const float*)d_in[12];

    int N = in_sizes[0] / 2;
    int E = in_sizes[1] / 2;

    float *p_agg, *p_hidden, *p_h2, *p_h;
    cudaGetSymbolAddress((void**)&p_agg, g_agg);
    cudaGetSymbolAddress((void**)&p_hidden, g_hidden);
    cudaGetSymbolAddress((void**)&p_h2, g_h2);
    cudaGetSymbolAddress((void**)&p_h, g_h);
    __nv_bfloat16 *pw1h, *pw1l, *pw2h, *pw2l;
    cudaGetSymbolAddress((void**)&pw1h, g_w1h);
    cudaGetSymbolAddress((void**)&pw1l, g_w1l);
    cudaGetSymbolAddress((void**)&pw2h, g_w2h);
    cudaGetSymbolAddress((void**)&pw2l, g_w2l);

    const int SMEM = 4 * 128 * SM_PITCH * 2;  // 139264 bytes
    cudaFuncSetAttribute(mma_gemm<true>,
                         cudaFuncAttributeMaxDynamicSharedMemorySize, SMEM);
    cudaFuncSetAttribute(mma_gemm<false>,
                         cudaFuncAttributeMaxDynamicSharedMemorySize, SMEM);

    int nb = (N + 255) / 256;

    // CSR build (by destination)
    k_zero_deg<<<(N + 255) / 256, 256>>>(N);
    k_count<<<(E + 255) / 256, 256>>>(ei, E);
    k_scan_block<<<nb, 256>>>(N);
    k_scan_top<<<1, 256>>>(nb);
    k_addoff<<<nb, 256>>>(N, E);
    k_fill<<<(E + 255) / 256, 256>>>(ei, E);

    // weight prep + atom encoder
    k_prep_w<<<(NLAYER * 256 * 128 + 255) / 256, 256>>>(W1, W2);
    k_atom<<<((size_t)N * D + 255) / 256, 256>>>(x, ae1, ae2, N);

    int mtiles = (N + 127) / 128;

    for (int l = 0; l < NLAYER; l++) {
        const float* be1L = be1 + (size_t)l * 7 * D;
        const float* be2L = be2 + (size_t)l * 4 * D;

        // aggregate (warp per node)
        int totalThreads = N * 32;
        k_aggregate<<<(totalThreads + 255) / 256, 256>>>(ei, ea, be1L, be2L, N, E);

        // MLP via mma.sync split-bf16
        dim3 g1(mtiles, 2);
        mma_gemm<true><<<g1, 256, SMEM>>>(
            p_agg, pw1h + (size_t)l * 32768, pw1l + (size_t)l * 32768,
            b1 + (size_t)l * 256, p_hidden, N, 128, 256);
        dim3 g2(mtiles, 1);
        mma_gemm<false><<<g2, 256, SMEM>>>(
            p_hidden, pw2h + (size_t)l * 32768, pw2l + (size_t)l * 32768,
            b2 + (size_t)l * 128, p_h2, N, 256, 128);

        // batchnorm (+relu except last layer)
        k_bn_zero<<<1, 256>>>();
        k_bn_stats<<<256, 128>>>(N);
        float* dst = (l == NLAYER - 1) ? (float*)d_out : p_h;
        k_bn_apply<<<((size_t)N * D + 255) / 256, 256>>>(
            dst, gamma + (size_t)l * D, beta + (size_t)l * D, N, l < NLAYER - 1);
    }
}

// round 7
// speedup vs baseline: 1.7558x; 1.2289x over previous
#include <cuda_runtime.h>
#include <cuda_fp16.h>
#include <cstdint>

#define D 128
#define MAXN 65536
#define MAXE 1048576
#define NLAYER 5

// ---------------- static scratch ----------------
__device__ float  g_h[(size_t)MAXN * D];        // atom encoder output (fp32)
__device__ float  g_h2[(size_t)MAXN * D];       // gemm2 output (fp32, pre-BN)
__device__ __half g_ah[(size_t)MAXN * D];       // agg hi
__device__ __half g_al[(size_t)MAXN * D];       // agg lo
__device__ __half g_hh[(size_t)MAXN * 2 * D];   // hidden hi
__device__ __half g_hl[(size_t)MAXN * 2 * D];   // hidden lo
__device__ int    g_deg[MAXN];
__device__ int    g_rowptr[MAXN + 1];
__device__ int    g_cursor[MAXN];
__device__ int    g_perm[MAXE];
__device__ int    g_bsum[512];
__device__ float  g_bnstat[2][256];             // [buf][0:128 sum, 128:256 sumsq]
__device__ __half g_w1h[NLAYER * 256 * 128];    // W1^T fp16 hi [n][k]
__device__ __half g_w1l[NLAYER * 256 * 128];    // W1^T fp16 lo
__device__ __half g_w2h[NLAYER * 128 * 256];    // W2^T fp16 hi [n][k]
__device__ __half g_w2l[NLAYER * 128 * 256];    // W2^T fp16 lo

// ---------------- CSR build ----------------
__global__ void k_zero_deg(int N) {
    int i = blockIdx.x * blockDim.x + threadIdx.x;
    if (i < N) g_deg[i] = 0;
}

__global__ void k_count(const int* __restrict__ ei, int E) {
    int e = blockIdx.x * blockDim.x + threadIdx.x;
    if (e < E) atomicAdd(&g_deg[ei[E + e]], 1);
}

__global__ void k_scan_block(int N) {
    __shared__ int s[256];
    int tid = threadIdx.x;
    int i = blockIdx.x * 256 + tid;
    int v = (i < N) ? g_deg[i] : 0;
    s[tid] = v;
    __syncthreads();
    #pragma unroll
    for (int off = 1; off < 256; off <<= 1) {
        int t = (tid >= off) ? s[tid - off] : 0;
        __syncthreads();
        s[tid] += t;
        __syncthreads();
    }
    if (i < N) g_rowptr[i] = s[tid] - v;
    if (tid == 255) g_bsum[blockIdx.x] = s[255];
}

__global__ void k_scan_top(int nb) {
    __shared__ int s[256];
    int tid = threadIdx.x;
    int v = (tid < nb) ? g_bsum[tid] : 0;
    s[tid] = v;
    __syncthreads();
    #pragma unroll
    for (int off = 1; off < 256; off <<= 1) {
        int t = (tid >= off) ? s[tid - off] : 0;
        __syncthreads();
        s[tid] += t;
        __syncthreads();
    }
    if (tid < nb) g_bsum[tid] = s[tid] - v;
}

__global__ void k_addoff(int N, int E) {
    int tid = threadIdx.x;
    int i = blockIdx.x * 256 + tid;
    if (i < N) {
        int r = g_rowptr[i] + g_bsum[blockIdx.x];
        g_rowptr[i] = r;
        g_cursor[i] = r;
    }
    if (i == 0) g_rowptr[N] = E;
}

__global__ void k_fill(const int* __restrict__ ei, int E) {
    int e = blockIdx.x * blockDim.x + threadIdx.x;
    if (e < E) {
        int dst = ei[E + e];
        int pos = atomicAdd(&g_cursor[dst], 1);
        g_perm[pos] = e;
    }
}

// ---------------- weight prep: transpose + fp16 hi/lo split ----------------
__global__ void k_prep_w(const float* __restrict__ W1, const float* __restrict__ W2) {
    int idx = blockIdx.x * blockDim.x + threadIdx.x;
    if (idx >= NLAYER * 256 * 128) return;
    int l = idx >> 15;
    int r = idx & 32767;
    {
        int n = r >> 7, k = r & 127;
        float v = W1[(size_t)l * 32768 + (size_t)k * 256 + n];
        __half h = __float2half_rn(v);
        g_w1h[idx] = h;
        g_w1l[idx] = __float2half_rn(v - __half2float(h));
    }
    {
        int n = r >> 8, k = r & 255;
        float v = W2[(size_t)l * 32768 + (size_t)k * 128 + n];
        __half h = __float2half_rn(v);
        g_w2h[idx] = h;
        g_w2l[idx] = __float2half_rn(v - __half2float(h));
    }
}

// ---------------- atom encoder ----------------
__global__ void k_atom(const int* __restrict__ x,
                       const float* __restrict__ ae1,
                       const float* __restrict__ ae2, int N) {
    int idx = blockIdx.x * blockDim.x + threadIdx.x;
    if (idx >= N * D) return;
    int n = idx >> 7;
    int d = idx & (D - 1);
    g_h[idx] = ae1[x[2 * n] * D + d] + ae2[x[2 * n + 1] * D + d];
}

// ---------------- aggregation (fused prev-layer BN+ReLU, split-fp16 out) ----
__global__ void k_aggregate(const int* __restrict__ ei,
                            const int* __restrict__ ea,
                            const float* __restrict__ be1,
                            const float* __restrict__ be2,
                            const float* __restrict__ srcfeat,
                            const float* __restrict__ bnstat_prev,
                            float* __restrict__ bnstat_cur,
                            const float* __restrict__ gammaP,
                            const float* __restrict__ betaP,
                            int N, int doBN) {
    if (blockIdx.x == 0 && threadIdx.x < 256) bnstat_cur[threadIdx.x] = 0.f;

    int gw = (blockIdx.x * blockDim.x + threadIdx.x) >> 5;
    int lane = threadIdx.x & 31;
    if (gw >= N) return;
    int n = gw;

    float4 scale = make_float4(1.f, 1.f, 1.f, 1.f);
    float4 shift = make_float4(0.f, 0.f, 0.f, 0.f);
    if (doBN) {
        float invN = 1.0f / (float)N;
        #pragma unroll
        for (int q = 0; q < 4; q++) {
            int c = lane * 4 + q;
            float mu = bnstat_prev[c] * invN;
            float var = bnstat_prev[128 + c] * invN - mu * mu;
            float istd = rsqrtf(var + 1e-5f);
            float sc = istd * gammaP[c];
            float sh = betaP[c] - mu * sc;
            ((float*)&scale)[q] = sc;
            ((float*)&shift)[q] = sh;
        }
    }

    const float4* h4 = (const float4*)srcfeat;

    float4 hv = h4[(size_t)n * 32 + lane];
    float4 acc;
    if (doBN) {
        acc.x = fmaxf(fmaf(hv.x, scale.x, shift.x), 0.f);
        acc.y = fmaxf(fmaf(hv.y, scale.y, shift.y), 0.f);
        acc.z = fmaxf(fmaf(hv.z, scale.z, shift.z), 0.f);
        acc.w = fmaxf(fmaf(hv.w, scale.w, shift.w), 0.f);
    } else {
        acc = hv;
    }
    float4 s1 = *(const float4*)&be1[6 * D + lane * 4];
    float4 s2 = *(const float4*)&be2[3 * D + lane * 4];
    acc.x += s1.x + s2.x; acc.y += s1.y + s2.y;
    acc.z += s1.z + s2.z; acc.w += s1.w + s2.w;

    int beg = g_rowptr[n];
    int end = g_rowptr[n + 1];
    for (int k = beg; k < end; k++) {
        int e  = g_perm[k];
        int s  = ei[e];
        int a0 = ea[2 * e];
        int a1 = ea[2 * e + 1];
        float4 xv = h4[(size_t)s * 32 + lane];
        float4 b1v = *(const float4*)&be1[a0 * D + lane * 4];
        float4 b2v = *(const float4*)&be2[a1 * D + lane * 4];
        if (doBN) {
            xv.x = fmaxf(fmaf(xv.x, scale.x, shift.x), 0.f);
            xv.y = fmaxf(fmaf(xv.y, scale.y, shift.y), 0.f);
            xv.z = fmaxf(fmaf(xv.z, scale.z, shift.z), 0.f);
            xv.w = fmaxf(fmaf(xv.w, scale.w, shift.w), 0.f);
        }
        acc.x += xv.x + b1v.x + b2v.x;
        acc.y += xv.y + b1v.y + b2v.y;
        acc.z += xv.z + b1v.z + b2v.z;
        acc.w += xv.w + b1v.w + b2v.w;
    }

    __half hh[4], hl[4];
    float* av = (float*)&acc;
    #pragma unroll
    for (int q = 0; q < 4; q++) {
        __half hi = __float2half_rn(av[q]);
        hh[q] = hi;
        hl[q] = __float2half_rn(av[q] - __half2float(hi));
    }
    *(uint2*)&g_ah[(size_t)n * D + lane * 4] = *(uint2*)hh;
    *(uint2*)&g_al[(size_t)n * D + lane * 4] = *(uint2*)hl;
}

// ---------------- mma.sync fp16 split GEMM (3 products) ----------------
// C = A @ W^T + bias; A = Ah + Al, W = Wh + Wl (fp16 pairs).
// D = Ah*Wh + Al*Wh + Ah*Wl in fp32 accum.
// CTA tile 128x128, 8 warps (2x4), warp 64x32, K chunked by 64 (pitch 72).
// EPI=0: store hidden split fp16 hi/lo with ReLU (GEMM1).
// EPI=1: store fp32 to C + fused BN stats atomics (GEMM2).

#define BK 64
#define SM_PITCH 72  // halves per row: 64 + 8 pad (144B, conflict-free)

__device__ __forceinline__ uint32_t smem_u32(const void* p) {
    uint32_t a;
    asm("{ .reg .u64 t; cvta.to.shared.u64 t, %1; cvt.u32.u64 %0, t; }"
        : "=r"(a) : "l"(p));
    return a;
}

__device__ __forceinline__ void ldmx4(uint32_t* r, uint32_t addr) {
    asm volatile("ldmatrix.sync.aligned.m8n8.x4.shared.b16 {%0,%1,%2,%3}, [%4];"
                 : "=r"(r[0]), "=r"(r[1]), "=r"(r[2]), "=r"(r[3]) : "r"(addr));
}

__device__ __forceinline__ void mma16816(float* c, const uint32_t* a,
                                         const uint32_t* b) {
    asm volatile(
        "mma.sync.aligned.m16n8k16.row.col.f32.f16.f16.f32 "
        "{%0,%1,%2,%3}, {%4,%5,%6,%7}, {%8,%9}, {%0,%1,%2,%3};"
        : "+f"(c[0]), "+f"(c[1]), "+f"(c[2]), "+f"(c[3])
        : "r"(a[0]), "r"(a[1]), "r"(a[2]), "r"(a[3]), "r"(b[0]), "r"(b[1]));
}

template <int EPI>
__global__ void __launch_bounds__(256, 2)
mma_gemm(const __half* __restrict__ Ah_g,
         const __half* __restrict__ Al_g,
         const __half* __restrict__ Wh_g,
         const __half* __restrict__ Wl_g,
         const float* __restrict__ bias,
         float* __restrict__ C,
         __half* __restrict__ Oh,
         __half* __restrict__ Ol,
         float* __restrict__ bnstat,
         int M, int K, int Nc) {
    extern __shared__ __align__(16) char smem[];
    const int SZ = 128 * SM_PITCH * 2;  // 18432 bytes per buffer
    char* pAh = smem;
    char* pAl = smem + SZ;
    char* pBh = smem + 2 * SZ;
    char* pBl = smem + 3 * SZ;
    uint32_t sAh = smem_u32(pAh), sAl = sAh + SZ, sBh = sAh + 2 * SZ,
             sBl = sAh + 3 * SZ;

    int tid = threadIdx.x;
    int lane = tid & 31, w = tid >> 5;
    int wm = (w & 1) * 64;
    int wn = (w >> 1) * 32;
    int m0 = blockIdx.x * 128;
    int n0 = blockIdx.y * 128;

    float acc[4][4][4];
    #pragma unroll
    for (int i = 0; i < 4; i++)
        #pragma unroll
        for (int j = 0; j < 4; j++)
            #pragma unroll
            for (int q = 0; q < 4; q++) acc[i][j][q] = 0.f;

    const int nchunk = K / BK;
    for (int c = 0; c < nchunk; c++) {
        if (c > 0) __syncthreads();
        int k0 = c * BK;

        // A tiles: 128 rows x 64 halves = 1024 16B-chunks, 4 iters
        #pragma unroll
        for (int it = 0; it < 4; it++) {
            int idx = tid + it * 256;
            int r = idx >> 3, q = idx & 7;
            uint4 vh = make_uint4(0, 0, 0, 0), vl = vh;
            if (m0 + r < M) {
                size_t gi = (size_t)(m0 + r) * K + k0 + q * 8;
                vh = *(const uint4*)(Ah_g + gi);
                vl = *(const uint4*)(Al_g + gi);
            }
            int boff = (r * SM_PITCH + q * 8) * 2;
            *(uint4*)(pAh + boff) = vh;
            *(uint4*)(pAl + boff) = vl;
        }
        // B tiles: 128 n-rows x 64 halves (hi + lo)
        #pragma unroll
        for (int it = 0; it < 4; it++) {
            int idx = tid + it * 256;
            int n = idx >> 3, q = idx & 7;
            size_t gi = (size_t)(n0 + n) * K + k0 + q * 8;
            int boff = (n * SM_PITCH + q * 8) * 2;
            *(uint4*)(pBh + boff) = *(const uint4*)(Wh_g + gi);
            *(uint4*)(pBl + boff) = *(const uint4*)(Wl_g + gi);
        }
        __syncthreads();

        #pragma unroll
        for (int ks = 0; ks < BK / 16; ks++) {
            uint32_t aH[4][4], aL[4][4], bH[4][2], bL[4][2];
            int arow = wm + (lane & 15);
            int acol = ks * 16 + (lane >> 4) * 8;
            #pragma unroll
            for (int i = 0; i < 4; i++) {
                uint32_t off = (uint32_t)(((arow + i * 16) * SM_PITCH + acol) * 2);
                ldmx4(aH[i], sAh + off);
                ldmx4(aL[i], sAl + off);
            }
            int brow = wn + ((lane >> 4) << 3) + (lane & 7);
            int bcol = ks * 16 + ((lane >> 3) & 1) * 8;
            #pragma unroll
            for (int p = 0; p < 2; p++) {
                uint32_t off = (uint32_t)(((brow + p * 16) * SM_PITCH + bcol) * 2);
                uint32_t t[4];
                ldmx4(t, sBh + off);
                bH[2 * p][0] = t[0]; bH[2 * p][1] = t[1];
                bH[2 * p + 1][0] = t[2]; bH[2 * p + 1][1] = t[3];
                ldmx4(t, sBl + off);
                bL[2 * p][0] = t[0]; bL[2 * p][1] = t[1];
                bL[2 * p + 1][0] = t[2]; bL[2 * p + 1][1] = t[3];
            }
            #pragma unroll
            for (int i = 0; i < 4; i++)
                #pragma unroll
                for (int j = 0; j < 4; j++) {
                    mma16816(acc[i][j], aH[i], bH[j]);
                    mma16816(acc[i][j], aL[i], bH[j]);
                    mma16816(acc[i][j], aH[i], bL[j]);
                }
        }
    }

    // ---------------- epilogue ----------------
    #pragma unroll
    for (int j = 0; j < 4; j++) {
        int col = n0 + wn + j * 8 + (lane & 3) * 2;
        float bx = __ldg(&bias[col]);
        float by = __ldg(&bias[col + 1]);
        float s0 = 0.f, s1 = 0.f, q0 = 0.f, q1 = 0.f;
        #pragma unroll
        for (int i = 0; i < 4; i++) {
            int r0 = m0 + wm + i * 16 + (lane >> 2);
            float v0 = acc[i][j][0] + bx, v1 = acc[i][j][1] + by;
            float v2 = acc[i][j][2] + bx, v3 = acc[i][j][3] + by;
            if (EPI == 0) {
                v0 = fmaxf(v0, 0.f); v1 = fmaxf(v1, 0.f);
                v2 = fmaxf(v2, 0.f); v3 = fmaxf(v3, 0.f);
                __half h0 = __float2half_rn(v0), h1 = __float2half_rn(v1);
                __half h2 = __float2half_rn(v2), h3 = __float2half_rn(v3);
                __half l0 = __float2half_rn(v0 - __half2float(h0));
                __half l1 = __float2half_rn(v1 - __half2float(h1));
                __half l2 = __float2half_rn(v2 - __half2float(h2));
                __half l3 = __float2half_rn(v3 - __half2float(h3));
                if (r0 < M) {
                    __half ph[2] = {h0, h1}, pl[2] = {l0, l1};
                    *(uint32_t*)&Oh[(size_t)r0 * Nc + col] = *(uint32_t*)ph;
                    *(uint32_t*)&Ol[(size_t)r0 * Nc + col] = *(uint32_t*)pl;
                }
                if (r0 + 8 < M) {
                    __half ph[2] = {h2, h3}, pl[2] = {l2, l3};
                    *(uint32_t*)&Oh[(size_t)(r0 + 8) * Nc + col] = *(uint32_t*)ph;
                    *(uint32_t*)&Ol[(size_t)(r0 + 8) * Nc + col] = *(uint32_t*)pl;
                }
            } else {
                if (r0 < M) {
                    *(float2*)&C[(size_t)r0 * Nc + col] = make_float2(v0, v1);
                    s0 += v0; s1 += v1; q0 += v0 * v0; q1 += v1 * v1;
                }
                if (r0 + 8 < M) {
                    *(float2*)&C[(size_t)(r0 + 8) * Nc + col] = make_float2(v2, v3);
                    s0 += v2; s1 += v3; q0 += v2 * v2; q1 += v3 * v3;
                }
            }
        }
        if (EPI == 1) {
            #pragma unroll
            for (int d = 4; d < 32; d <<= 1) {
                s0 += __shfl_xor_sync(0xffffffff, s0, d);
                s1 += __shfl_xor_sync(0xffffffff, s1, d);
                q0 += __shfl_xor_sync(0xffffffff, q0, d);
                q1 += __shfl_xor_sync(0xffffffff, q1, d);
            }
            if (lane < 4) {
                atomicAdd(&bnstat[col], s0);
                atomicAdd(&bnstat[col + 1], s1);
                atomicAdd(&bnstat[128 + col], q0);
                atomicAdd(&bnstat[128 + col + 1], q1);
            }
        }
    }
}

// ---------------- final BN apply (layer 4, no relu) ----------------
__global__ void k_bn_apply(float* __restrict__ dst,
                           const float* __restrict__ stat,
                           const float* __restrict__ gamma,
                           const float* __restrict__ beta, int N) {
    int idx = blockIdx.x * blockDim.x + threadIdx.x;
    if (idx >= N * D) return;
    int c = idx & (D - 1);
    float invN = 1.0f / (float)N;
    float mu = stat[c] * invN;
    float var = stat[128 + c] * invN - mu * mu;
    float istd = rsqrtf(var + 1e-5f);
    dst[idx] = (g_h2[idx] - mu) * istd * gamma[c] + beta[c];
}

// ---------------- launch ----------------
extern "C" void kernel_launch(void* const* d_in, const int* in_sizes, int n_in,
                              void* d_out, int out_size) {
    const int*   x     = (const int*)d_in[0];
    const int*   ei    = (const int*)d_in[1];
    const int*   ea    = (const int*)d_in[2];
    const float* ae1   = (const float*)d_in[3];
    const float* ae2   = (const float*)d_in[4];
    const float* be1   = (const float*)d_in[5];
    const float* be2   = (const float*)d_in[6];
    const float* W1    = (const float*)d_in[7];
    const float* b1    = (const float*)d_in[8];
    const float* W2    = (const float*)d_in[9];
    const float* b2    = (const float*)d_in[10];
    const float* gamma = (const float*)d_in[11];
    const float* beta  = (const float*)d_in[12];

    int N = in_sizes[0] / 2;
    int E = in_sizes[1] / 2;

    float *p_h, *p_h2, *p_bn;
    __half *p_ah, *p_al, *p_hh, *p_hl, *p_w1h, *p_w1l, *p_w2h, *p_w2l;
    cudaGetSymbolAddress((void**)&p_h, g_h);
    cudaGetSymbolAddress((void**)&p_h2, g_h2);
    cudaGetSymbolAddress((void**)&p_bn, g_bnstat);
    cudaGetSymbolAddress((void**)&p_ah, g_ah);
    cudaGetSymbolAddress((void**)&p_al, g_al);
    cudaGetSymbolAddress((void**)&p_hh, g_hh);
    cudaGetSymbolAddress((void**)&p_hl, g_hl);
    cudaGetSymbolAddress((void**)&p_w1h, g_w1h);
    cudaGetSymbolAddress((void**)&p_w1l, g_w1l);
    cudaGetSymbolAddress((void**)&p_w2h, g_w2h);
    cudaGetSymbolAddress((void**)&p_w2l, g_w2l);

    const int SMEM = 4 * 128 * SM_PITCH * 2;  // 73728 bytes
    cudaFuncSetAttribute(mma_gemm<0>,
                         cudaFuncAttributeMaxDynamicSharedMemorySize, SMEM);
    cudaFuncSetAttribute(mma_gemm<1>,
                         cudaFuncAttributeMaxDynamicSharedMemorySize, SMEM);

    int nb = (N + 255) / 256;

    // CSR build
    k_zero_deg<<<(N + 255) / 256, 256>>>(N);
    k_count<<<(E + 255) / 256, 256>>>(ei, E);
    k_scan_block<<<nb, 256>>>(N);
    k_scan_top<<<1, 256>>>(nb);
    k_addoff<<<nb, 256>>>(N, E);
    k_fill<<<(E + 255) / 256, 256>>>(ei, E);

    k_prep_w<<<(NLAYER * 256 * 128 + 255) / 256, 256>>>(W1, W2);
    k_atom<<<((size_t)N * D + 255) / 256, 256>>>(x, ae1, ae2, N);

    int mtiles = (N + 127) / 128;

    for (int l = 0; l < NLAYER; l++) {
        const float* be1L = be1 + (size_t)l * 7 * D;
        const float* be2L = be2 + (size_t)l * 4 * D;
        float* bn_cur  = p_bn + (l & 1) * 256;
        float* bn_prev = p_bn + ((l - 1) & 1) * 256;

        // aggregate: fused prev-layer BN+ReLU; writes split fp16; zeroes bn_cur
        int totalThreads = N * 32;
        k_aggregate<<<(totalThreads + 255) / 256, 256>>>(
            ei, ea, be1L, be2L,
            (l == 0) ? p_h : p_h2,
            bn_prev, bn_cur,
            gamma + (size_t)(l > 0 ? l - 1 : 0) * D,
            beta + (size_t)(l > 0 ? l - 1 : 0) * D,
            N, l > 0);

        // GEMM1: hidden = relu(agg @ W1 + b1), split fp16 out
        dim3 g1(mtiles, 2);
        mma_gemm<0><<<g1, 256, SMEM>>>(
            p_ah, p_al, p_w1h + (size_t)l * 32768, p_w1l + (size_t)l * 32768,
            b1 + (size_t)l * 256, nullptr, p_hh, p_hl, nullptr, N, 128, 256);

        // GEMM2: h2 = hidden @ W2 + b2 (fp32) + fused BN stats
        dim3 g2(mtiles, 1);
        mma_gemm<1><<<g2, 256, SMEM>>>(
            p_hh, p_hl, p_w2h + (size_t)l * 32768, p_w2l + (size_t)l * 32768,
            b2 + (size_t)l * 128, p_h2, nullptr, nullptr, bn_cur, N, 256, 128);
    }

    // final output: BN (no relu) of layer 4
    k_bn_apply<<<((size_t)N * D + 255) / 256, 256>>>(
        (float*)d_out, p_bn + (4 & 1) * 256,
        gamma + (size_t)4 * D, beta + (size_t)4 * D, N);
}